// round 14
// baseline (speedup 1.0000x reference)
#include <cuda_runtime.h>
#include <cstdint>

// ---------------------------------------------------------------------------
// StochLinear v11: exact JAX threefry bits -> CSA-popcount GEMM, with
// bitgen/GEMM OVERLAP via l-split heterogeneous kernel:
//   k1: gen bits l0-3            (GEMM chunks 0-7 depend only on these)
//   k2: MEGA: 1024 GEMM-lo CTAs (chunks 0-7 -> Sp[0]) interleaved with
//       1536 bitgen-hi CTAs (l4-7) -- bitgen fills the GEMM's idle alu slots
//   k3: GEMM-hi, 2048 CTAs (chunks 8-11 -> Sp[1], 12-15 -> Sp[2])
//   k4: exact epilogue: out = 0.5*(S0+S1+S2) - 0.25*(sA+sB) + 2048 + bias
// ---------------------------------------------------------------------------

#define B_DIM 4096
#define K_DIM 2048
#define N_DIM 2048
#define ROW_WORDS 512              // 8 l-slices * 64 words
#define CW   32                    // words per k-chunk (128 B)
#define PITCH 144                  // 128 B row + 16 B pad
#define BM 128
#define BN 64
#define A_TILE_B (BM * PITCH)      // 18432
#define B_TILE_B (BN * PITCH)      // 9216
#define STAGE_B  (A_TILE_B + B_TILE_B)  // 27648
#define NSTG 4
#define SMEM_BYTES (NSTG * STAGE_B)     // 110592

__device__ uint32_t g_Apack[(size_t)B_DIM * ROW_WORDS]; // 8 MB
__device__ uint32_t g_Wpack[(size_t)N_DIM * ROW_WORDS]; // 4 MB
__device__ int g_sA[B_DIM];
__device__ int g_sB[N_DIM];
__device__ int g_Sp[3][(size_t)B_DIM * N_DIM];          // 96 MB partials

#ifdef __CUDA_ARCH__
#define ROTL(x, r) __funnelshift_l((x), (x), (r))
#else
#define ROTL(x, r) (((x) << (r)) | ((x) >> (32 - (r))))
#endif

// ---------------- Threefry-2x32 (20 rounds) --------------------------------
__host__ __device__ __forceinline__ void tf2x32(uint32_t k0, uint32_t k1,
                                                uint32_t x0, uint32_t x1,
                                                uint32_t &o0, uint32_t &o1)
{
    uint32_t ks2 = k0 ^ k1 ^ 0x1BD11BDAu;
    x0 += k0; x1 += k1;
#define TFR(r) { x0 += x1; x1 = ROTL(x1, r); x1 ^= x0; }
    TFR(13) TFR(15) TFR(26) TFR(6)
    x0 += k1;  x1 += ks2 + 1u;
    TFR(17) TFR(29) TFR(16) TFR(24)
    x0 += ks2; x1 += k0 + 2u;
    TFR(13) TFR(15) TFR(26) TFR(6)
    x0 += k0;  x1 += k1 + 3u;
    TFR(17) TFR(29) TFR(16) TFR(24)
    x0 += k1;  x1 += ks2 + 4u;
    TFR(13) TFR(15) TFR(26) TFR(6)
    x0 += ks2; x1 += k0 + 5u;
#undef TFR
    o0 = x0; o1 = x1;
}

// bit = (uniform(bits) < p)  ==  ((bits>>9) < ceil(p * 2^23))   (exact)
__device__ __forceinline__ uint32_t prob_to_int(float p)
{
    return (uint32_t)__float2int_ru(p * 8388608.0f);
}

// ---------------- bitgen bodies (4 l-slices per call) -----------------------
// A: (L,B,K), ctr = (l<<23)|(b<<11)|k
__device__ void genA_body(const float* __restrict__ x,
                          uint32_t k0, uint32_t k1, int rowblk, int l0)
{
    int t  = threadIdx.x;
    int b  = rowblk * 4 + (t >> 6);
    int kw = t & 63;
    const float* xr = x + (size_t)b * K_DIM + (size_t)kw * 32;

    uint32_t words[4] = {0,0,0,0};
    for (int j = 0; j < 32; ++j) {
        float v = xr[j];
        float p = fminf(fmaxf((v + 1.0f) * 0.5f, 0.0f), 1.0f);
        uint32_t ip = prob_to_int(p);
        uint32_t base = ((uint32_t)b << 11) | (uint32_t)(kw * 32 + j);
#pragma unroll
        for (int li = 0; li < 4; ++li) {
            uint32_t o0, o1;
            tf2x32(k0, k1, 0u, ((uint32_t)(l0 + li) << 23) | base, o0, o1);
            if (((o0 ^ o1) >> 9) < ip) words[li] |= (1u << j);
        }
    }
    int cnt = 0;
#pragma unroll
    for (int li = 0; li < 4; ++li) {
        g_Apack[(size_t)b * ROW_WORDS + (l0 + li) * 64 + kw] = words[li];
        cnt += __popc(words[li]);
    }
#pragma unroll
    for (int o = 16; o > 0; o >>= 1) cnt += __shfl_down_sync(0xffffffffu, cnt, o);
    if ((t & 31) == 0) atomicAdd(&g_sA[b], cnt);
}

// W: (L,K,N), ctr = (l<<22)|(k<<11)|n
__device__ void genW_body(const float* __restrict__ w,
                          uint32_t k0, uint32_t k1, int rowblk, int l0)
{
    int t  = threadIdx.x;
    int nn = rowblk * 4 + (t >> 6);
    int kw = t & 63;
    const float* wr = w + (size_t)nn * K_DIM + (size_t)kw * 32;

    uint32_t words[4] = {0,0,0,0};
    for (int j = 0; j < 32; ++j) {
        float v = wr[j];
        float p = fminf(fmaxf((v + 1.0f) * 0.5f, 0.0f), 1.0f);
        uint32_t ip = prob_to_int(p);
        uint32_t kk = (uint32_t)(kw * 32 + j);
        uint32_t base = (kk << 11) | (uint32_t)nn;
#pragma unroll
        for (int li = 0; li < 4; ++li) {
            uint32_t o0, o1;
            tf2x32(k0, k1, 0u, ((uint32_t)(l0 + li) << 22) | base, o0, o1);
            if (((o0 ^ o1) >> 9) < ip) words[li] |= (1u << j);
        }
    }
    int cnt = 0;
#pragma unroll
    for (int li = 0; li < 4; ++li) {
        g_Wpack[(size_t)nn * ROW_WORDS + (l0 + li) * 64 + kw] = words[li];
        cnt += __popc(words[li]);
    }
#pragma unroll
    for (int o = 16; o > 0; o >>= 1) cnt += __shfl_down_sync(0xffffffffu, cnt, o);
    if ((t & 31) == 0) atomicAdd(&g_sB[nn], cnt);
}

__global__ void __launch_bounds__(256) gen_bits_A_lo(const float* __restrict__ x,
                                                     uint32_t k0, uint32_t k1)
{
    genA_body(x, k0, k1, blockIdx.x, 0);
}
__global__ void __launch_bounds__(256) gen_bits_W_lo(const float* __restrict__ w,
                                                     uint32_t k0, uint32_t k1)
{
    genW_body(w, k0, k1, blockIdx.x, 0);
}

__global__ void zero_counts()
{
    int i = blockIdx.x * blockDim.x + threadIdx.x;
    if (i < B_DIM) g_sA[i] = 0;
    if (i < N_DIM) g_sB[i] = 0;
}

// ---------------- popc GEMM body (v10 core, runtime chunk range) ------------
__device__ __forceinline__ uint32_t smem_u32(const void* p)
{
    uint32_t a;
    asm("{ .reg .u64 t; cvta.to.shared.u64 t, %1; cvt.u32.u64 %0, t; }" : "=r"(a) : "l"(p));
    return a;
}
__device__ __forceinline__ void cp16(uint32_t dst, const void* src)
{
    asm volatile("cp.async.cg.shared.global [%0], [%1], 16;" :: "r"(dst), "l"(src));
}
#define CP_COMMIT() asm volatile("cp.async.commit_group;" ::: "memory")
#define CP_WAIT2()  asm volatile("cp.async.wait_group 2;" ::: "memory")

__device__ __forceinline__ uint32_t xor3(uint32_t a, uint32_t b, uint32_t c)
{
    uint32_t r;
    asm("lop3.b32 %0, %1, %2, %3, 0x96;" : "=r"(r) : "r"(a), "r"(b), "r"(c));
    return r;
}
__device__ __forceinline__ uint32_t maj3(uint32_t a, uint32_t b, uint32_t c)
{
    uint32_t r;
    asm("lop3.b32 %0, %1, %2, %3, 0xE8;" : "=r"(r) : "r"(a), "r"(b), "r"(c));
    return r;
}

// CSA 7->3 + 1 naive over 8 AND-words: 4 POPC instead of 8.
__device__ __forceinline__ void csa8(int &acc,
                                     const uint4 &a0, const uint4 &a1,
                                     const uint4 &b0, const uint4 &b1)
{
    uint32_t x0 = a0.x & b0.x, x1 = a0.y & b0.y;
    uint32_t x2 = a0.z & b0.z, x3 = a0.w & b0.w;
    uint32_t x4 = a1.x & b1.x, x5 = a1.y & b1.y;
    uint32_t x6 = a1.z & b1.z, x7 = a1.w & b1.w;
    uint32_t s0 = xor3(x0, x1, x2), c0 = maj3(x0, x1, x2);
    uint32_t s1 = xor3(x3, x4, x5), c1 = maj3(x3, x4, x5);
    uint32_t S  = xor3(s0, s1, x6), c2 = maj3(s0, s1, x6);
    uint32_t C  = xor3(c0, c1, c2), CC = maj3(c0, c1, c2);
    acc += __popc(S) + __popc(x7)
         + 2 * __popc(C) + 4 * __popc(CC);
}

__device__ __forceinline__ uint4 lds128(uint32_t addr)
{
    uint4 v;
    asm volatile("ld.shared.v4.u32 {%0,%1,%2,%3}, [%4];"
                 : "=r"(v.x), "=r"(v.y), "=r"(v.z), "=r"(v.w) : "r"(addr));
    return v;
}

__device__ void gemm_body(char* smraw, int bx, int by,
                          int kt0, int nch, int* __restrict__ Sout)
{
    uint32_t sb = smem_u32(smraw);

    int tid = threadIdx.x;
    int tx  = tid & 15;        // 16 col-groups (cols tx + 16j, j=0..3)
    int ty  = tid >> 4;        // 16 row-groups (rows ty + 16i, i=0..7)
    int row0 = by * BM;
    int col0 = bx * BN;

    // stage loader: 1536 cp16 tasks (A: 1024, B: 512), 6 per thread
    auto load_stage = [&](int kt, int s) {
        uint32_t dst0 = sb + (uint32_t)s * STAGE_B;
#pragma unroll
        for (int q = 0; q < 6; ++q) {
            int task = tid + q * 256;          // 0..1535
            if (task < 1024) {
                int r = task >> 3, ch = task & 7;
                cp16(dst0 + (uint32_t)r * PITCH + (uint32_t)(ch << 4),
                     &g_Apack[(size_t)(row0 + r) * ROW_WORDS + kt * CW + ch * 4]);
            } else {
                int rem = task - 1024;
                int r = rem >> 3, ch = rem & 7;
                cp16(dst0 + A_TILE_B + (uint32_t)r * PITCH + (uint32_t)(ch << 4),
                     &g_Wpack[(size_t)(col0 + r) * ROW_WORDS + kt * CW + ch * 4]);
            }
        }
    };

    int acc[8][4];
#pragma unroll
    for (int i = 0; i < 8; ++i)
#pragma unroll
        for (int j = 0; j < 4; ++j) acc[i][j] = 0;

    load_stage(kt0 + 0, 0); CP_COMMIT();
    load_stage(kt0 + 1, 1); CP_COMMIT();
    load_stage(kt0 + 2, 2); CP_COMMIT();

    // 4-stage ring, distance-3 prefetch, ONE barrier per chunk.
#pragma unroll 1
    for (int t = 0; t < nch; ++t) {
        CP_WAIT2();
        __syncthreads();

        uint32_t base = sb + (uint32_t)(t & 3) * STAGE_B;
        uint32_t Ab = base + (uint32_t)ty * PITCH;
        uint32_t Bb = base + A_TILE_B + (uint32_t)tx * PITCH;

#pragma unroll 1
        for (int g = 0; g < 4; ++g) {           // 8 words = 32 B per row
            uint4 b0[4], b1[4];                  // B cols tx+16j, held over i
#pragma unroll
            for (int j = 0; j < 4; ++j) {
                uint32_t rb = Bb + j * (16 * PITCH) + g * 32;
                b0[j] = lds128(rb);
                b1[j] = lds128(rb + 16);
            }
#pragma unroll
            for (int ih = 0; ih < 2; ++ih) {     // i in halves of 4 (regs)
                uint4 a0[4], a1[4];
#pragma unroll
                for (int i4 = 0; i4 < 4; ++i4) {
                    uint32_t rb = Ab + (ih * 4 + i4) * (16 * PITCH) + g * 32;
                    a0[i4] = lds128(rb);
                    a1[i4] = lds128(rb + 16);
                }
#pragma unroll
                for (int i4 = 0; i4 < 4; ++i4)
#pragma unroll
                    for (int j = 0; j < 4; ++j)
                        csa8(acc[ih * 4 + i4][j], a0[i4], a1[i4], b0[j], b1[j]);
            }
        }
        if (t + 3 < nch) load_stage(kt0 + t + 3, (t + 3) & 3);
        CP_COMMIT();   // commit every iter (possibly empty) keeps counts aligned
    }

    // write partial S with plain stores (each (row,col,buffer) unique)
#pragma unroll
    for (int i = 0; i < 8; ++i) {
        int row = row0 + ty + 16 * i;
#pragma unroll
        for (int j = 0; j < 4; ++j) {
            int col = col0 + tx + 16 * j;
            Sout[(size_t)row * N_DIM + col] = acc[i][j];
        }
    }
}

// ---------------- MEGA: GEMM-lo CTAs interleaved with bitgen-hi CTAs --------
// 2560 blocks, pattern per 5: [GEMM, GEMM, genA, genA, genW]
__global__ void __launch_bounds__(256, 2) mega_lo(const float* __restrict__ x,
                                                  const float* __restrict__ w,
                                                  uint32_t a0, uint32_t a1,
                                                  uint32_t b0, uint32_t b1)
{
    extern __shared__ char smraw[];
    int bid = blockIdx.x;
    int m = bid % 5;
    int q = bid / 5;           // 0..511
    if (m < 2) {
        int idx = q * 2 + m;   // 0..1023
        gemm_body(smraw, idx & 31, idx >> 5, 0, 8, g_Sp[0]);
    } else if (m < 4) {
        genA_body(x, a0, a1, q * 2 + (m - 2), 4);   // l4-7
    } else {
        genW_body(w, b0, b1, q, 4);                 // l4-7
    }
}

// ---------------- GEMM-hi: chunks 8-11 -> Sp[1], 12-15 -> Sp[2] -------------
__global__ void __launch_bounds__(256, 2) gemm_hi(void)
{
    extern __shared__ char smraw[];
    int z = blockIdx.z;
    gemm_body(smraw, blockIdx.x, blockIdx.y, 8 + 4 * z, 4, g_Sp[1 + z]);
}

// ---------------- exact epilogue --------------------------------------------
__global__ void __launch_bounds__(256) ep_out(const float* __restrict__ bias,
                                              float* __restrict__ out)
{
    int idx = blockIdx.x * 256 + threadIdx.x;      // 1M threads, 4 cols each
    int row = idx >> 9;
    int c4  = (idx & 511) * 4;
    float sa = (float)__ldg(&g_sA[row]);
    int4 s0 = *reinterpret_cast<const int4*>(&g_Sp[0][(size_t)row * N_DIM + c4]);
    int4 s1 = *reinterpret_cast<const int4*>(&g_Sp[1][(size_t)row * N_DIM + c4]);
    int4 s2 = *reinterpret_cast<const int4*>(&g_Sp[2][(size_t)row * N_DIM + c4]);
    float4 bv = *reinterpret_cast<const float4*>(&bias[c4]);
    int4 sbv = *reinterpret_cast<const int4*>(&g_sB[c4]);
    float4 ov;
    ov.x = 0.5f * (float)(s0.x + s1.x + s2.x) - 0.25f * (sa + (float)sbv.x) + 2048.0f + bv.x;
    ov.y = 0.5f * (float)(s0.y + s1.y + s2.y) - 0.25f * (sa + (float)sbv.y) + 2048.0f + bv.y;
    ov.z = 0.5f * (float)(s0.z + s1.z + s2.z) - 0.25f * (sa + (float)sbv.z) + 2048.0f + bv.z;
    ov.w = 0.5f * (float)(s0.w + s1.w + s2.w) - 0.25f * (sa + (float)sbv.w) + 2048.0f + bv.w;
    *reinterpret_cast<float4*>(&out[(size_t)row * N_DIM + c4]) = ov;
}

// ---------------------------------------------------------------------------
extern "C" void kernel_launch(void* const* d_in, const int* in_sizes, int n_in,
                              void* d_out, int out_size)
{
    const float* x    = (const float*)d_in[0];
    const float* w    = (const float*)d_in[1];
    const float* bias = (const float*)d_in[2];
    float* out        = (float*)d_out;

    // jax.random.split(jax.random.key(42)), partitionable (foldlike)
    uint32_t kA0, kA1, kB0, kB1;
    tf2x32(0u, 42u, 0u, 0u, kA0, kA1);
    tf2x32(0u, 42u, 0u, 1u, kB0, kB1);

    cudaFuncSetAttribute(mega_lo,
                         cudaFuncAttributeMaxDynamicSharedMemorySize, SMEM_BYTES);
    cudaFuncSetAttribute(gemm_hi,
                         cudaFuncAttributeMaxDynamicSharedMemorySize, SMEM_BYTES);

    zero_counts<<<16, 256>>>();
    gen_bits_W_lo<<<N_DIM / 4, 256>>>(w, kB0, kB1);            // l0-3
    gen_bits_A_lo<<<B_DIM / 4, 256>>>(x, kA0, kA1);            // l0-3
    mega_lo<<<2560, 256, SMEM_BYTES>>>(x, w, kA0, kA1, kB0, kB1);
    gemm_hi<<<dim3(32, 32, 2), 256, SMEM_BYTES>>>();
    ep_out<<<(B_DIM * N_DIM / 4) / 256, 256>>>(bias, out);
}

// round 15
// speedup vs baseline: 1.0414x; 1.0414x over previous
#include <cuda_runtime.h>
#include <cstdint>

// ---------------------------------------------------------------------------
// StochLinear v12: exact JAX threefry bits -> bit-packed CSA-popcount GEMM.
//   out[b,n] = 0.5*S - 0.25*(sA[b]+sB[n]) + 2048 + bias[n]      (exact fp32)
// v12 = v10 GEMM (proven: 556us, ~94% of alu/xu dual-pipe floor) + leaner
// bitgen: float4 input loads, atomic-free sA/sB (smem reduce + plain store),
// zero_counts kernel eliminated.
// ---------------------------------------------------------------------------

#define B_DIM 4096
#define K_DIM 2048
#define N_DIM 2048
#define ROW_WORDS 512              // 8 l-slices * 64 words
#define CW   32                    // words per k-chunk (128 B)
#define NCH  (ROW_WORDS / CW)      // 16 total; 8 per split
#define KSPLIT 2
#define NCHS (NCH / KSPLIT)        // 8
#define PITCH 144                  // 128 B row + 16 B pad
#define BM 128
#define BN 64
#define A_TILE_B (BM * PITCH)      // 18432
#define B_TILE_B (BN * PITCH)      // 9216
#define STAGE_B  (A_TILE_B + B_TILE_B)  // 27648
#define NSTG 4
#define SMEM_BYTES (NSTG * STAGE_B)     // 110592

__device__ uint32_t g_Apack[(size_t)B_DIM * ROW_WORDS]; // 8 MB
__device__ uint32_t g_Wpack[(size_t)N_DIM * ROW_WORDS]; // 4 MB
__device__ int g_sA[B_DIM];
__device__ int g_sB[N_DIM];
__device__ int g_Sp[KSPLIT][(size_t)B_DIM * N_DIM];     // 64 MB partials

#ifdef __CUDA_ARCH__
#define ROTL(x, r) __funnelshift_l((x), (x), (r))
#else
#define ROTL(x, r) (((x) << (r)) | ((x) >> (32 - (r))))
#endif

// ---------------- Threefry-2x32 (20 rounds) --------------------------------
__host__ __device__ __forceinline__ void tf2x32(uint32_t k0, uint32_t k1,
                                                uint32_t x0, uint32_t x1,
                                                uint32_t &o0, uint32_t &o1)
{
    uint32_t ks2 = k0 ^ k1 ^ 0x1BD11BDAu;
    x0 += k0; x1 += k1;
#define TFR(r) { x0 += x1; x1 = ROTL(x1, r); x1 ^= x0; }
    TFR(13) TFR(15) TFR(26) TFR(6)
    x0 += k1;  x1 += ks2 + 1u;
    TFR(17) TFR(29) TFR(16) TFR(24)
    x0 += ks2; x1 += k0 + 2u;
    TFR(13) TFR(15) TFR(26) TFR(6)
    x0 += k0;  x1 += k1 + 3u;
    TFR(17) TFR(29) TFR(16) TFR(24)
    x0 += k1;  x1 += ks2 + 4u;
    TFR(13) TFR(15) TFR(26) TFR(6)
    x0 += ks2; x1 += k0 + 5u;
#undef TFR
    o0 = x0; o1 = x1;
}

// bit = (uniform(bits) < p)  ==  ((bits>>9) < ceil(p * 2^23))   (exact)
__device__ __forceinline__ uint32_t prob_to_int(float p)
{
    return (uint32_t)__float2int_ru(p * 8388608.0f);
}

// ---------------- bitgen A: (L,B,K), ctr = (l<<23)|(b<<11)|k ----------------
// Block = 4 rows (2 warps per row). Atomic-free counts via smem reduce.
__global__ void __launch_bounds__(256) gen_bits_A(const float* __restrict__ x,
                                                  uint32_t k0, uint32_t k1)
{
    __shared__ int scnt[8];
    int t  = threadIdx.x;
    int b  = blockIdx.x * 4 + (t >> 6);
    int kw = t & 63;
    const float4* xr4 = reinterpret_cast<const float4*>(
        x + (size_t)b * K_DIM + (size_t)kw * 32);

    uint32_t words[8] = {0,0,0,0,0,0,0,0};
#pragma unroll 2
    for (int jq = 0; jq < 8; ++jq) {
        float4 v4 = xr4[jq];
        float vv[4] = {v4.x, v4.y, v4.z, v4.w};
#pragma unroll
        for (int jj = 0; jj < 4; ++jj) {
            int j = jq * 4 + jj;
            float p = fminf(fmaxf((vv[jj] + 1.0f) * 0.5f, 0.0f), 1.0f);
            uint32_t ip = prob_to_int(p);
            uint32_t base = ((uint32_t)b << 11) | (uint32_t)(kw * 32 + j);
#pragma unroll
            for (int l = 0; l < 8; ++l) {
                uint32_t o0, o1;
                tf2x32(k0, k1, 0u, ((uint32_t)l << 23) | base, o0, o1);
                if (((o0 ^ o1) >> 9) < ip) words[l] |= (1u << j);
            }
        }
    }
    int cnt = 0;
#pragma unroll
    for (int l = 0; l < 8; ++l) {
        g_Apack[(size_t)b * ROW_WORDS + l * 64 + kw] = words[l];
        cnt += __popc(words[l]);
    }
#pragma unroll
    for (int o = 16; o > 0; o >>= 1) cnt += __shfl_down_sync(0xffffffffu, cnt, o);
    if ((t & 31) == 0) scnt[t >> 5] = cnt;
    __syncthreads();
    if (t < 4) g_sA[blockIdx.x * 4 + t] = scnt[2 * t] + scnt[2 * t + 1];
}

// ---------------- bitgen W: (L,K,N), ctr = (l<<22)|(k<<11)|n ----------------
__global__ void __launch_bounds__(256) gen_bits_W(const float* __restrict__ w,
                                                  uint32_t k0, uint32_t k1)
{
    __shared__ int scnt[8];
    int t  = threadIdx.x;
    int nn = blockIdx.x * 4 + (t >> 6);
    int kw = t & 63;
    const float4* wr4 = reinterpret_cast<const float4*>(
        w + (size_t)nn * K_DIM + (size_t)kw * 32);

    uint32_t words[8] = {0,0,0,0,0,0,0,0};
#pragma unroll 2
    for (int jq = 0; jq < 8; ++jq) {
        float4 v4 = wr4[jq];
        float vv[4] = {v4.x, v4.y, v4.z, v4.w};
#pragma unroll
        for (int jj = 0; jj < 4; ++jj) {
            int j = jq * 4 + jj;
            float p = fminf(fmaxf((vv[jj] + 1.0f) * 0.5f, 0.0f), 1.0f);
            uint32_t ip = prob_to_int(p);
            uint32_t kk = (uint32_t)(kw * 32 + j);
            uint32_t base = (kk << 11) | (uint32_t)nn;
#pragma unroll
            for (int l = 0; l < 8; ++l) {
                uint32_t o0, o1;
                tf2x32(k0, k1, 0u, ((uint32_t)l << 22) | base, o0, o1);
                if (((o0 ^ o1) >> 9) < ip) words[l] |= (1u << j);
            }
        }
    }
    int cnt = 0;
#pragma unroll
    for (int l = 0; l < 8; ++l) {
        g_Wpack[(size_t)nn * ROW_WORDS + l * 64 + kw] = words[l];
        cnt += __popc(words[l]);
    }
#pragma unroll
    for (int o = 16; o > 0; o >>= 1) cnt += __shfl_down_sync(0xffffffffu, cnt, o);
    if ((t & 31) == 0) scnt[t >> 5] = cnt;
    __syncthreads();
    if (t < 4) g_sB[blockIdx.x * 4 + t] = scnt[2 * t] + scnt[2 * t + 1];
}

// ---------------- popc GEMM (v10, unchanged) ---------------------------------
__device__ __forceinline__ uint32_t smem_u32(const void* p)
{
    uint32_t a;
    asm("{ .reg .u64 t; cvta.to.shared.u64 t, %1; cvt.u32.u64 %0, t; }" : "=r"(a) : "l"(p));
    return a;
}
__device__ __forceinline__ void cp16(uint32_t dst, const void* src)
{
    asm volatile("cp.async.cg.shared.global [%0], [%1], 16;" :: "r"(dst), "l"(src));
}
#define CP_COMMIT() asm volatile("cp.async.commit_group;" ::: "memory")
#define CP_WAIT2()  asm volatile("cp.async.wait_group 2;" ::: "memory")

__device__ __forceinline__ uint32_t xor3(uint32_t a, uint32_t b, uint32_t c)
{
    uint32_t r;
    asm("lop3.b32 %0, %1, %2, %3, 0x96;" : "=r"(r) : "r"(a), "r"(b), "r"(c));
    return r;
}
__device__ __forceinline__ uint32_t maj3(uint32_t a, uint32_t b, uint32_t c)
{
    uint32_t r;
    asm("lop3.b32 %0, %1, %2, %3, 0xE8;" : "=r"(r) : "r"(a), "r"(b), "r"(c));
    return r;
}

// CSA 7->3 + 1 naive over 8 AND-words: 4 POPC instead of 8.
__device__ __forceinline__ void csa8(int &acc,
                                     const uint4 &a0, const uint4 &a1,
                                     const uint4 &b0, const uint4 &b1)
{
    uint32_t x0 = a0.x & b0.x, x1 = a0.y & b0.y;
    uint32_t x2 = a0.z & b0.z, x3 = a0.w & b0.w;
    uint32_t x4 = a1.x & b1.x, x5 = a1.y & b1.y;
    uint32_t x6 = a1.z & b1.z, x7 = a1.w & b1.w;
    uint32_t s0 = xor3(x0, x1, x2), c0 = maj3(x0, x1, x2);
    uint32_t s1 = xor3(x3, x4, x5), c1 = maj3(x3, x4, x5);
    uint32_t S  = xor3(s0, s1, x6), c2 = maj3(s0, s1, x6);
    uint32_t C  = xor3(c0, c1, c2), CC = maj3(c0, c1, c2);
    acc += __popc(S) + __popc(x7)
         + 2 * __popc(C) + 4 * __popc(CC);
}

__device__ __forceinline__ uint4 lds128(uint32_t addr)
{
    uint4 v;
    asm volatile("ld.shared.v4.u32 {%0,%1,%2,%3}, [%4];"
                 : "=r"(v.x), "=r"(v.y), "=r"(v.z), "=r"(v.w) : "r"(addr));
    return v;
}

__global__ void __launch_bounds__(256, 2) popc_gemm12(void)
{
    extern __shared__ char smraw[];
    uint32_t sb = smem_u32(smraw);

    int tid = threadIdx.x;
    int tx  = tid & 15;        // 16 col-groups (cols tx + 16j, j=0..3)
    int ty  = tid >> 4;        // 16 row-groups (rows ty + 16i, i=0..7)
    int row0 = blockIdx.y * BM;
    int col0 = blockIdx.x * BN;
    int kt0  = blockIdx.z * NCHS;   // split-K offset (0 or 8)
    int* Sout = g_Sp[blockIdx.z];

    // stage loader: 1536 cp16 tasks (A: 1024, B: 512), 6 per thread
    auto load_stage = [&](int kt, int s) {
        uint32_t dst0 = sb + (uint32_t)s * STAGE_B;
#pragma unroll
        for (int q = 0; q < 6; ++q) {
            int task = tid + q * 256;          // 0..1535
            if (task < 1024) {
                int r = task >> 3, ch = task & 7;
                cp16(dst0 + (uint32_t)r * PITCH + (uint32_t)(ch << 4),
                     &g_Apack[(size_t)(row0 + r) * ROW_WORDS + kt * CW + ch * 4]);
            } else {
                int rem = task - 1024;
                int r = rem >> 3, ch = rem & 7;
                cp16(dst0 + A_TILE_B + (uint32_t)r * PITCH + (uint32_t)(ch << 4),
                     &g_Wpack[(size_t)(col0 + r) * ROW_WORDS + kt * CW + ch * 4]);
            }
        }
    };

    int acc[8][4];
#pragma unroll
    for (int i = 0; i < 8; ++i)
#pragma unroll
        for (int j = 0; j < 4; ++j) acc[i][j] = 0;

    load_stage(kt0 + 0, 0); CP_COMMIT();
    load_stage(kt0 + 1, 1); CP_COMMIT();
    load_stage(kt0 + 2, 2); CP_COMMIT();

    // 4-stage ring, distance-3 prefetch, ONE barrier per chunk.
    for (int t = 0; t < NCHS; ++t) {
        CP_WAIT2();
        __syncthreads();

        uint32_t base = sb + (uint32_t)(t & 3) * STAGE_B;
        uint32_t Ab = base + (uint32_t)ty * PITCH;
        uint32_t Bb = base + A_TILE_B + (uint32_t)tx * PITCH;

#pragma unroll 1
        for (int g = 0; g < 4; ++g) {           // 8 words = 32 B per row
            uint4 b0[4], b1[4];                  // B cols tx+16j, held over i
#pragma unroll
            for (int j = 0; j < 4; ++j) {
                uint32_t rb = Bb + j * (16 * PITCH) + g * 32;
                b0[j] = lds128(rb);
                b1[j] = lds128(rb + 16);
            }
#pragma unroll
            for (int ih = 0; ih < 2; ++ih) {     // i in halves of 4 (regs)
                uint4 a0[4], a1[4];
#pragma unroll
                for (int i4 = 0; i4 < 4; ++i4) {
                    uint32_t rb = Ab + (ih * 4 + i4) * (16 * PITCH) + g * 32;
                    a0[i4] = lds128(rb);
                    a1[i4] = lds128(rb + 16);
                }
#pragma unroll
                for (int i4 = 0; i4 < 4; ++i4)
#pragma unroll
                    for (int j = 0; j < 4; ++j)
                        csa8(acc[ih * 4 + i4][j], a0[i4], a1[i4], b0[j], b1[j]);
            }
        }
        if (t + 3 < NCHS) load_stage(kt0 + t + 3, (t + 3) & 3);
        CP_COMMIT();   // commit every iter (possibly empty) keeps counts aligned
    }

    // write partial S with plain stores (each (row,col,z) unique -> no race)
#pragma unroll
    for (int i = 0; i < 8; ++i) {
        int row = row0 + ty + 16 * i;
#pragma unroll
        for (int j = 0; j < 4; ++j) {
            int col = col0 + tx + 16 * j;
            Sout[(size_t)row * N_DIM + col] = acc[i][j];
        }
    }
}

// ---------------- exact epilogue --------------------------------------------
__global__ void __launch_bounds__(256) ep_out(const float* __restrict__ bias,
                                              float* __restrict__ out)
{
    int idx = blockIdx.x * 256 + threadIdx.x;      // 1M threads, 4 cols each
    int row = idx >> 9;
    int c4  = (idx & 511) * 4;
    float sa = (float)__ldg(&g_sA[row]);
    int4 s0 = *reinterpret_cast<const int4*>(&g_Sp[0][(size_t)row * N_DIM + c4]);
    int4 s1 = *reinterpret_cast<const int4*>(&g_Sp[1][(size_t)row * N_DIM + c4]);
    float4 bv = *reinterpret_cast<const float4*>(&bias[c4]);
    int4 sbv = *reinterpret_cast<const int4*>(&g_sB[c4]);
    float4 ov;
    ov.x = 0.5f * (float)(s0.x + s1.x) - 0.25f * (sa + (float)sbv.x) + 2048.0f + bv.x;
    ov.y = 0.5f * (float)(s0.y + s1.y) - 0.25f * (sa + (float)sbv.y) + 2048.0f + bv.y;
    ov.z = 0.5f * (float)(s0.z + s1.z) - 0.25f * (sa + (float)sbv.z) + 2048.0f + bv.z;
    ov.w = 0.5f * (float)(s0.w + s1.w) - 0.25f * (sa + (float)sbv.w) + 2048.0f + bv.w;
    *reinterpret_cast<float4*>(&out[(size_t)row * N_DIM + c4]) = ov;
}

// ---------------------------------------------------------------------------
extern "C" void kernel_launch(void* const* d_in, const int* in_sizes, int n_in,
                              void* d_out, int out_size)
{
    const float* x    = (const float*)d_in[0];
    const float* w    = (const float*)d_in[1];
    const float* bias = (const float*)d_in[2];
    float* out        = (float*)d_out;

    // jax.random.split(jax.random.key(42)), partitionable (foldlike)
    uint32_t kA0, kA1, kB0, kB1;
    tf2x32(0u, 42u, 0u, 0u, kA0, kA1);
    tf2x32(0u, 42u, 0u, 1u, kB0, kB1);

    cudaFuncSetAttribute(popc_gemm12,
                         cudaFuncAttributeMaxDynamicSharedMemorySize, SMEM_BYTES);

    gen_bits_A<<<B_DIM / 4, 256>>>(x, kA0, kA1);
    gen_bits_W<<<N_DIM / 4, 256>>>(w, kB0, kB1);
    popc_gemm12<<<dim3(N_DIM / BN, B_DIM / BM, KSPLIT), 256, SMEM_BYTES>>>();
    ep_out<<<(B_DIM * N_DIM / 4) / 256, 256>>>(bias, out);
}

// round 16
// speedup vs baseline: 1.0483x; 1.0067x over previous
#include <cuda_runtime.h>
#include <cstdint>

// ---------------------------------------------------------------------------
// StochLinear v13: exact JAX threefry bits -> bit-packed CSA-popcount GEMM.
//   out[b,n] = 0.5*S - 0.25*(sA[b]+sB[n]) + 2048 + bias[n]      (exact fp32)
// v13 = v12 with: (1) int16 split-K partials (max 8192 < 2^15 -> exact),
// halving epilogue traffic; (2) merged A/W bitgen launch (one tail, one
// launch gap). GEMM core unchanged (94% of alu/xu dual-pipe floor).
// ---------------------------------------------------------------------------

#define B_DIM 4096
#define K_DIM 2048
#define N_DIM 2048
#define ROW_WORDS 512              // 8 l-slices * 64 words
#define CW   32                    // words per k-chunk (128 B)
#define NCH  (ROW_WORDS / CW)      // 16 total; 8 per split
#define KSPLIT 2
#define NCHS (NCH / KSPLIT)        // 8
#define PITCH 144                  // 128 B row + 16 B pad
#define BM 128
#define BN 64
#define A_TILE_B (BM * PITCH)      // 18432
#define B_TILE_B (BN * PITCH)      // 9216
#define STAGE_B  (A_TILE_B + B_TILE_B)  // 27648
#define NSTG 4
#define SMEM_BYTES (NSTG * STAGE_B)     // 110592

__device__ uint32_t g_Apack[(size_t)B_DIM * ROW_WORDS]; // 8 MB
__device__ uint32_t g_Wpack[(size_t)N_DIM * ROW_WORDS]; // 4 MB
__device__ int g_sA[B_DIM];
__device__ int g_sB[N_DIM];
__device__ short g_Sp[KSPLIT][(size_t)B_DIM * N_DIM];   // 32 MB partials (i16)

#ifdef __CUDA_ARCH__
#define ROTL(x, r) __funnelshift_l((x), (x), (r))
#else
#define ROTL(x, r) (((x) << (r)) | ((x) >> (32 - (r))))
#endif

// ---------------- Threefry-2x32 (20 rounds) --------------------------------
__host__ __device__ __forceinline__ void tf2x32(uint32_t k0, uint32_t k1,
                                                uint32_t x0, uint32_t x1,
                                                uint32_t &o0, uint32_t &o1)
{
    uint32_t ks2 = k0 ^ k1 ^ 0x1BD11BDAu;
    x0 += k0; x1 += k1;
#define TFR(r) { x0 += x1; x1 = ROTL(x1, r); x1 ^= x0; }
    TFR(13) TFR(15) TFR(26) TFR(6)
    x0 += k1;  x1 += ks2 + 1u;
    TFR(17) TFR(29) TFR(16) TFR(24)
    x0 += ks2; x1 += k0 + 2u;
    TFR(13) TFR(15) TFR(26) TFR(6)
    x0 += k0;  x1 += k1 + 3u;
    TFR(17) TFR(29) TFR(16) TFR(24)
    x0 += k1;  x1 += ks2 + 4u;
    TFR(13) TFR(15) TFR(26) TFR(6)
    x0 += ks2; x1 += k0 + 5u;
#undef TFR
    o0 = x0; o1 = x1;
}

// bit = (uniform(bits) < p)  ==  ((bits>>9) < ceil(p * 2^23))   (exact)
__device__ __forceinline__ uint32_t prob_to_int(float p)
{
    return (uint32_t)__float2int_ru(p * 8388608.0f);
}

// ---------------- merged bitgen: blocks [0,1024) -> A, [1024,1536) -> W -----
// A: (L,B,K), ctr = (l<<23)|(b<<11)|k ; W: (L,K,N), ctr = (l<<22)|(k<<11)|n
__global__ void __launch_bounds__(256) gen_bits(const float* __restrict__ x,
                                                const float* __restrict__ w,
                                                uint32_t a0, uint32_t a1,
                                                uint32_t b0, uint32_t b1)
{
    __shared__ int scnt[8];
    int t  = threadIdx.x;
    int kw = t & 63;
    bool isA = blockIdx.x < (B_DIM / 4);
    int rowblk = isA ? blockIdx.x : (blockIdx.x - B_DIM / 4);
    int row = rowblk * 4 + (t >> 6);

    const float* src = isA ? x : w;
    const float4* r4 = reinterpret_cast<const float4*>(
        src + (size_t)row * K_DIM + (size_t)kw * 32);
    uint32_t k0 = isA ? a0 : b0;
    uint32_t k1 = isA ? a1 : b1;

    uint32_t words[8] = {0,0,0,0,0,0,0,0};
#pragma unroll 2
    for (int jq = 0; jq < 8; ++jq) {
        float4 v4 = r4[jq];
        float vv[4] = {v4.x, v4.y, v4.z, v4.w};
#pragma unroll
        for (int jj = 0; jj < 4; ++jj) {
            int j = jq * 4 + jj;
            float p = fminf(fmaxf((vv[jj] + 1.0f) * 0.5f, 0.0f), 1.0f);
            uint32_t ip = prob_to_int(p);
            int kk = kw * 32 + j;
            // A: ctr = (l<<23) | (row<<11) | kk ; W: ctr = (l<<22) | (kk<<11) | row
            uint32_t base = isA ? (((uint32_t)row << 11) | (uint32_t)kk)
                                : (((uint32_t)kk << 11) | (uint32_t)row);
            uint32_t lsh = isA ? 23 : 22;
#pragma unroll
            for (int l = 0; l < 8; ++l) {
                uint32_t o0, o1;
                tf2x32(k0, k1, 0u, ((uint32_t)l << lsh) | base, o0, o1);
                if (((o0 ^ o1) >> 9) < ip) words[l] |= (1u << j);
            }
        }
    }
    uint32_t* dst = isA ? g_Apack : g_Wpack;
    int cnt = 0;
#pragma unroll
    for (int l = 0; l < 8; ++l) {
        dst[(size_t)row * ROW_WORDS + l * 64 + kw] = words[l];
        cnt += __popc(words[l]);
    }
#pragma unroll
    for (int o = 16; o > 0; o >>= 1) cnt += __shfl_down_sync(0xffffffffu, cnt, o);
    if ((t & 31) == 0) scnt[t >> 5] = cnt;
    __syncthreads();
    if (t < 4) {
        int v = scnt[2 * t] + scnt[2 * t + 1];
        if (isA) g_sA[rowblk * 4 + t] = v;
        else     g_sB[rowblk * 4 + t] = v;
    }
}

// ---------------- popc GEMM (v10 core, int16 partial stores) -----------------
__device__ __forceinline__ uint32_t smem_u32(const void* p)
{
    uint32_t a;
    asm("{ .reg .u64 t; cvta.to.shared.u64 t, %1; cvt.u32.u64 %0, t; }" : "=r"(a) : "l"(p));
    return a;
}
__device__ __forceinline__ void cp16(uint32_t dst, const void* src)
{
    asm volatile("cp.async.cg.shared.global [%0], [%1], 16;" :: "r"(dst), "l"(src));
}
#define CP_COMMIT() asm volatile("cp.async.commit_group;" ::: "memory")
#define CP_WAIT2()  asm volatile("cp.async.wait_group 2;" ::: "memory")

__device__ __forceinline__ uint32_t xor3(uint32_t a, uint32_t b, uint32_t c)
{
    uint32_t r;
    asm("lop3.b32 %0, %1, %2, %3, 0x96;" : "=r"(r) : "r"(a), "r"(b), "r"(c));
    return r;
}
__device__ __forceinline__ uint32_t maj3(uint32_t a, uint32_t b, uint32_t c)
{
    uint32_t r;
    asm("lop3.b32 %0, %1, %2, %3, 0xE8;" : "=r"(r) : "r"(a), "r"(b), "r"(c));
    return r;
}

// CSA 7->3 + 1 naive over 8 AND-words: 4 POPC instead of 8.
__device__ __forceinline__ void csa8(int &acc,
                                     const uint4 &a0, const uint4 &a1,
                                     const uint4 &b0, const uint4 &b1)
{
    uint32_t x0 = a0.x & b0.x, x1 = a0.y & b0.y;
    uint32_t x2 = a0.z & b0.z, x3 = a0.w & b0.w;
    uint32_t x4 = a1.x & b1.x, x5 = a1.y & b1.y;
    uint32_t x6 = a1.z & b1.z, x7 = a1.w & b1.w;
    uint32_t s0 = xor3(x0, x1, x2), c0 = maj3(x0, x1, x2);
    uint32_t s1 = xor3(x3, x4, x5), c1 = maj3(x3, x4, x5);
    uint32_t S  = xor3(s0, s1, x6), c2 = maj3(s0, s1, x6);
    uint32_t C  = xor3(c0, c1, c2), CC = maj3(c0, c1, c2);
    acc += __popc(S) + __popc(x7)
         + 2 * __popc(C) + 4 * __popc(CC);
}

__device__ __forceinline__ uint4 lds128(uint32_t addr)
{
    uint4 v;
    asm volatile("ld.shared.v4.u32 {%0,%1,%2,%3}, [%4];"
                 : "=r"(v.x), "=r"(v.y), "=r"(v.z), "=r"(v.w) : "r"(addr));
    return v;
}

__global__ void __launch_bounds__(256, 2) popc_gemm13(void)
{
    extern __shared__ char smraw[];
    uint32_t sb = smem_u32(smraw);

    int tid = threadIdx.x;
    int tx  = tid & 15;        // 16 col-groups (cols tx + 16j, j=0..3)
    int ty  = tid >> 4;        // 16 row-groups (rows ty + 16i, i=0..7)
    int row0 = blockIdx.y * BM;
    int col0 = blockIdx.x * BN;
    int kt0  = blockIdx.z * NCHS;   // split-K offset (0 or 8)
    short* Sout = g_Sp[blockIdx.z];

    // stage loader: 1536 cp16 tasks (A: 1024, B: 512), 6 per thread
    auto load_stage = [&](int kt, int s) {
        uint32_t dst0 = sb + (uint32_t)s * STAGE_B;
#pragma unroll
        for (int q = 0; q < 6; ++q) {
            int task = tid + q * 256;          // 0..1535
            if (task < 1024) {
                int r = task >> 3, ch = task & 7;
                cp16(dst0 + (uint32_t)r * PITCH + (uint32_t)(ch << 4),
                     &g_Apack[(size_t)(row0 + r) * ROW_WORDS + kt * CW + ch * 4]);
            } else {
                int rem = task - 1024;
                int r = rem >> 3, ch = rem & 7;
                cp16(dst0 + A_TILE_B + (uint32_t)r * PITCH + (uint32_t)(ch << 4),
                     &g_Wpack[(size_t)(col0 + r) * ROW_WORDS + kt * CW + ch * 4]);
            }
        }
    };

    int acc[8][4];
#pragma unroll
    for (int i = 0; i < 8; ++i)
#pragma unroll
        for (int j = 0; j < 4; ++j) acc[i][j] = 0;

    load_stage(kt0 + 0, 0); CP_COMMIT();
    load_stage(kt0 + 1, 1); CP_COMMIT();
    load_stage(kt0 + 2, 2); CP_COMMIT();

    // 4-stage ring, distance-3 prefetch, ONE barrier per chunk.
    for (int t = 0; t < NCHS; ++t) {
        CP_WAIT2();
        __syncthreads();

        uint32_t base = sb + (uint32_t)(t & 3) * STAGE_B;
        uint32_t Ab = base + (uint32_t)ty * PITCH;
        uint32_t Bb = base + A_TILE_B + (uint32_t)tx * PITCH;

#pragma unroll 1
        for (int g = 0; g < 4; ++g) {           // 8 words = 32 B per row
            uint4 b0[4], b1[4];                  // B cols tx+16j, held over i
#pragma unroll
            for (int j = 0; j < 4; ++j) {
                uint32_t rb = Bb + j * (16 * PITCH) + g * 32;
                b0[j] = lds128(rb);
                b1[j] = lds128(rb + 16);
            }
#pragma unroll
            for (int ih = 0; ih < 2; ++ih) {     // i in halves of 4 (regs)
                uint4 a0[4], a1[4];
#pragma unroll
                for (int i4 = 0; i4 < 4; ++i4) {
                    uint32_t rb = Ab + (ih * 4 + i4) * (16 * PITCH) + g * 32;
                    a0[i4] = lds128(rb);
                    a1[i4] = lds128(rb + 16);
                }
#pragma unroll
                for (int i4 = 0; i4 < 4; ++i4)
#pragma unroll
                    for (int j = 0; j < 4; ++j)
                        csa8(acc[ih * 4 + i4][j], a0[i4], a1[i4], b0[j], b1[j]);
            }
        }
        if (t + 3 < NCHS) load_stage(kt0 + t + 3, (t + 3) & 3);
        CP_COMMIT();   // commit every iter (possibly empty) keeps counts aligned
    }

    // write partial S (int16, max 8192: exact) with plain stores
#pragma unroll
    for (int i = 0; i < 8; ++i) {
        int row = row0 + ty + 16 * i;
#pragma unroll
        for (int j = 0; j < 4; ++j) {
            int col = col0 + tx + 16 * j;
            Sout[(size_t)row * N_DIM + col] = (short)acc[i][j];
        }
    }
}

// ---------------- exact epilogue --------------------------------------------
__global__ void __launch_bounds__(256) ep_out(const float* __restrict__ bias,
                                              float* __restrict__ out)
{
    int idx = blockIdx.x * 256 + threadIdx.x;      // 1M threads, 4 cols each
    int row = idx >> 9;
    int c4  = (idx & 511) * 4;
    float sa = (float)__ldg(&g_sA[row]);
    short4 s0 = *reinterpret_cast<const short4*>(&g_Sp[0][(size_t)row * N_DIM + c4]);
    short4 s1 = *reinterpret_cast<const short4*>(&g_Sp[1][(size_t)row * N_DIM + c4]);
    float4 bv = *reinterpret_cast<const float4*>(&bias[c4]);
    int4 sbv = *reinterpret_cast<const int4*>(&g_sB[c4]);
    float4 ov;
    ov.x = 0.5f * (float)(s0.x + s1.x) - 0.25f * (sa + (float)sbv.x) + 2048.0f + bv.x;
    ov.y = 0.5f * (float)(s0.y + s1.y) - 0.25f * (sa + (float)sbv.y) + 2048.0f + bv.y;
    ov.z = 0.5f * (float)(s0.z + s1.z) - 0.25f * (sa + (float)sbv.z) + 2048.0f + bv.z;
    ov.w = 0.5f * (float)(s0.w + s1.w) - 0.25f * (sa + (float)sbv.w) + 2048.0f + bv.w;
    *reinterpret_cast<float4*>(&out[(size_t)row * N_DIM + c4]) = ov;
}

// ---------------------------------------------------------------------------
extern "C" void kernel_launch(void* const* d_in, const int* in_sizes, int n_in,
                              void* d_out, int out_size)
{
    const float* x    = (const float*)d_in[0];
    const float* w    = (const float*)d_in[1];
    const float* bias = (const float*)d_in[2];
    float* out        = (float*)d_out;

    // jax.random.split(jax.random.key(42)), partitionable (foldlike)
    uint32_t kA0, kA1, kB0, kB1;
    tf2x32(0u, 42u, 0u, 0u, kA0, kA1);
    tf2x32(0u, 42u, 0u, 1u, kB0, kB1);

    cudaFuncSetAttribute(popc_gemm13,
                         cudaFuncAttributeMaxDynamicSharedMemorySize, SMEM_BYTES);

    gen_bits<<<(B_DIM + N_DIM) / 4, 256>>>(x, w, kA0, kA1, kB0, kB1);
    popc_gemm13<<<dim3(N_DIM / BN, B_DIM / BM, KSPLIT), 256, SMEM_BYTES>>>();
    ep_out<<<(B_DIM * N_DIM / 4) / 256, 256>>>(bias, out);
}